// round 9
// baseline (speedup 1.0000x reference)
#include <cuda_runtime.h>
#include <math.h>

#define MAX_RAYS 65536
__device__ int g_seg[MAX_RAYS + 1];

typedef unsigned long long ull;

// ---- packed f32x2 helpers (Blackwell) -------------------------------------
__device__ __forceinline__ ull f2fma(ull a, ull b, ull c) {
    ull d;
    asm("fma.rn.f32x2 %0, %1, %2, %3;" : "=l"(d) : "l"(a), "l"(b), "l"(c));
    return d;
}
__device__ __forceinline__ ull f2add(ull a, ull b) {
    ull d;
    asm("add.rn.f32x2 %0, %1, %2;" : "=l"(d) : "l"(a), "l"(b));
    return d;
}
__device__ __forceinline__ ull f2pack(float lo, float hi) {
    ull d;
    asm("mov.b64 %0, {%1, %2};" : "=l"(d) : "f"(lo), "f"(hi));
    return d;
}
__device__ __forceinline__ void f2unpack(ull v, float& lo, float& hi) {
    asm("mov.b64 {%0, %1}, %2;" : "=f"(lo), "=f"(hi) : "l"(v));
}
#define ABSMASK 0x7FFFFFFF7FFFFFFFULL

// ---------------------------------------------------------------------------
// Kernel A: segment starts from sorted ray_indices (searchsorted).
// ---------------------------------------------------------------------------
__global__ void seg_boundary_kernel(const int* __restrict__ ri, int S, int n_rays) {
    const int i = blockIdx.x * blockDim.x + threadIdx.x;
    if (i >= S) return;
    const int r  = ri[i];
    const int rp = (i == 0) ? -1 : ri[i - 1];
    for (int rr = rp + 1; rr <= r; ++rr) g_seg[rr] = i;
    if (i == S - 1) {
        for (int rr = r + 1; rr <= n_rays; ++rr) g_seg[rr] = S;
    }
}

// ---------------------------------------------------------------------------
// Kernel B: one warp per ray. MLP collapsed to 1-D in t with per-ray exact
// t-bounds; constant-sign units folded into (A,C); active units compacted
// into per-warp shared pair list sQ[p] = {u2, v2} (one LDS.128 per pair).
// Main loop: 64-sample chunks (2 samples/lane) share each weight load.
// Opacity telescopes to 1 - exp(-total); only depth-num needs reduction.
// ---------------------------------------------------------------------------
__global__ void __launch_bounds__(256, 4) render_kernel(
    const float* __restrict__ rays_o,
    const float* __restrict__ rays_d,
    const float* __restrict__ W1,
    const float* __restrict__ b1,
    const float* __restrict__ W2,
    const float* __restrict__ b2,
    const float* __restrict__ t_starts,
    const float* __restrict__ t_ends,
    float* __restrict__ out,
    int n_rays)
{
    __shared__ ulonglong2 sQ[8][36];   // per-warp active pair list {u2, v2}

    const int wlocal  = threadIdx.x >> 5;
    const int lane    = threadIdx.x & 31;
    const int warp_id = (blockIdx.x * blockDim.x + threadIdx.x) >> 5;
    if (warp_id >= n_rays) return;
    const int r = warp_id;

    const int start = g_seg[r];
    const int end   = g_seg[r + 1];

    const float ox = __ldg(&rays_o[3 * r    ]);
    const float oy = __ldg(&rays_o[3 * r + 1]);
    const float oz = __ldg(&rays_o[3 * r + 2]);
    const float dx = __ldg(&rays_d[3 * r    ]);
    const float dy = __ldg(&rays_d[3 * r + 1]);
    const float dz = __ldg(&rays_d[3 * r + 2]);

    // ---- pre-pass: exact per-ray min/max of tm -----------------------------
    float ta = __int_as_float(0x7F800000);
    float tb = 0.f;
    for (int i0 = start; i0 < end; i0 += 32) {
        const int i = i0 + lane;
        if (i < end) {
            const float tm = 0.5f * (t_starts[i] + t_ends[i]);
            ta = fminf(ta, tm);
            tb = fmaxf(tb, tm);
        }
    }
    #pragma unroll
    for (int off = 16; off; off >>= 1) {
        ta = fminf(ta, __shfl_xor_sync(0xffffffffu, ta, off));
        tb = fmaxf(tb, __shfl_xor_sync(0xffffffffu, tb, off));
    }

    // ---- per-ray precompute (lane handles units 2*lane, 2*lane+1) ---------
    float A = 0.f, C = 0.f;
    float u0, v0, u1, v1;
    bool act0, act1, pos0, pos1;
    {
        const int j = 2 * lane;
        #pragma unroll
        for (int k = 0; k < 2; ++k) {
            const int jj = j + k;
            const float w1x = __ldg(&W1[jj]);
            const float w1y = __ldg(&W1[64 + jj]);
            const float w1z = __ldg(&W1[128 + jj]);
            const float bb  = __ldg(&b1[jj]);
            const float w2v = __ldg(&W2[jj]);
            const float hw  = 0.5f * w2v;

            const float a = fmaf(dx, w1x, fmaf(dy, w1y, dz * w1z));
            const float c = fmaf(ox, w1x, fmaf(oy, w1y, fmaf(oz, w1z, bb)));
            const float u = hw * a;
            const float v = hw * c;

            A += u;
            C += v;

            const float ya = fmaf(u, ta, v);
            const float yb = fmaf(u, tb, v);
            const bool act = (((__float_as_uint(ya) ^ __float_as_uint(yb)) >> 31) & 1u) != 0u;
            if (!act) {
                const float f = copysignf(1.f, ya + yb) * copysignf(1.f, w2v);
                A = fmaf(f, u, A);
                C = fmaf(f, v, C);
            }
            if (k == 0) { u0 = u; v0 = v; act0 = act; pos0 = (w2v >= 0.f); }
            else        { u1 = u; v1 = v; act1 = act; pos1 = (w2v >= 0.f); }
        }

        #pragma unroll
        for (int off = 16; off; off >>= 1) {
            A += __shfl_xor_sync(0xffffffffu, A, off);
            C += __shfl_xor_sync(0xffffffffu, C, off);
        }
        C += __ldg(b2);
    }

    // ---- ballot compaction into packed pair list ---------------------------
    // pair p floats: [u_lo, u_hi, v_lo, v_hi] at float offsets 4p..4p+3
    float* qF = (float*)sQ[wlocal];

    const unsigned bp0 = __ballot_sync(0xffffffffu, act0 && pos0);
    const unsigned bn0 = __ballot_sync(0xffffffffu, act0 && !pos0);
    const unsigned bp1 = __ballot_sync(0xffffffffu, act1 && pos1);
    const unsigned bn1 = __ballot_sync(0xffffffffu, act1 && !pos1);
    const int cP0 = __popc(bp0), cN0 = __popc(bn0);
    const int cP1 = __popc(bp1), cN1 = __popc(bn1);
    const int nPos = cP0 + cP1;
    const int nNeg = cN0 + cN1;
    const int negBase = (nPos + 1) & ~1;

    const unsigned mlt = (1u << lane) - 1u;
    if (act0) {
        const int ix = pos0 ? __popc(bp0 & mlt) : (negBase + __popc(bn0 & mlt));
        qF[4 * (ix >> 1) + (ix & 1)]     = u0;
        qF[4 * (ix >> 1) + 2 + (ix & 1)] = v0;
    }
    if (act1) {
        const int ix = pos1 ? (cP0 + __popc(bp1 & mlt))
                            : (negBase + cN0 + __popc(bn1 & mlt));
        qF[4 * (ix >> 1) + (ix & 1)]     = u1;
        qF[4 * (ix >> 1) + 2 + (ix & 1)] = v1;
    }
    if (lane == 0) {
        if (nPos & 1) {
            const int ix = nPos;
            qF[4 * (ix >> 1) + (ix & 1)]     = 0.f;
            qF[4 * (ix >> 1) + 2 + (ix & 1)] = 0.f;
        }
        if (nNeg & 1) {
            const int ix = negBase + nNeg;
            qF[4 * (ix >> 1) + (ix & 1)]     = 0.f;
            qF[4 * (ix >> 1) + 2 + (ix & 1)] = 0.f;
        }
    }
    __syncwarp();

    const int pPos      = (nPos + 1) >> 1;
    const int pNegStart = negBase >> 1;
    const int pNegEnd   = pNegStart + ((nNeg + 1) >> 1);
    const ulonglong2* qq = sQ[wlocal];

    float carry = 0.f;
    float dnum  = 0.f;

    for (int i0 = start; i0 < end; i0 += 64) {
        const int  iA = i0 + lane;
        const bool vA = (iA < end);
        const int  icA = vA ? iA : (end - 1);
        const float tsA = t_starts[icA];
        const float teA = t_ends[icA];
        const float tmA = 0.5f * (tsA + teA);
        const float dtA = teA - tsA;
        const ull   t2A = f2pack(tmA, tmA);

        const bool anyB = (i0 + 32 < end);   // warp-uniform
        float sA, sB = 0.f, tmB = 0.f;

        if (anyB) {
            const int  iB = i0 + 32 + lane;
            const bool vB = (iB < end);
            const int  icB = vB ? iB : (end - 1);
            const float tsB = t_starts[icB];
            const float teB = t_ends[icB];
            tmB = 0.5f * (tsB + teB);
            const float dtB = teB - tsB;
            const ull   t2B = f2pack(tmB, tmB);

            ull aPA = 0ull, aPB = 0ull, aNA = 0ull, aNB = 0ull;
            #pragma unroll 2
            for (int p = 0; p < pPos; ++p) {
                const ulonglong2 Q = qq[p];
                const ull yA = f2fma(t2A, Q.x, Q.y);
                aPA = f2add(aPA, yA & ABSMASK);
                const ull yB = f2fma(t2B, Q.x, Q.y);
                aPB = f2add(aPB, yB & ABSMASK);
            }
            #pragma unroll 2
            for (int p = pNegStart; p < pNegEnd; ++p) {
                const ulonglong2 Q = qq[p];
                const ull yA = f2fma(t2A, Q.x, Q.y);
                aNA = f2add(aNA, yA & ABSMASK);
                const ull yB = f2fma(t2B, Q.x, Q.y);
                aNB = f2add(aNB, yB & ABSMASK);
            }
            float x, y;
            f2unpack(aPA, x, y); float accA = x + y;
            f2unpack(aNA, x, y); accA -= (x + y);
            accA += fmaf(A, tmA, C);
            f2unpack(aPB, x, y); float accB = x + y;
            f2unpack(aNB, x, y); accB -= (x + y);
            accB += fmaf(A, tmB, C);

            const float spA = fmaxf(accA, 0.f) + __logf(1.f + __expf(-fabsf(accA)));
            const float spB = fmaxf(accB, 0.f) + __logf(1.f + __expf(-fabsf(accB)));
            sA = vA ? spA * dtA : 0.f;
            sB = vB ? spB * dtB : 0.f;
        } else {
            ull aPA = 0ull, aNA = 0ull;
            #pragma unroll 2
            for (int p = 0; p < pPos; ++p) {
                const ulonglong2 Q = qq[p];
                const ull yA = f2fma(t2A, Q.x, Q.y);
                aPA = f2add(aPA, yA & ABSMASK);
            }
            #pragma unroll 2
            for (int p = pNegStart; p < pNegEnd; ++p) {
                const ulonglong2 Q = qq[p];
                const ull yA = f2fma(t2A, Q.x, Q.y);
                aNA = f2add(aNA, yA & ABSMASK);
            }
            float x, y;
            f2unpack(aPA, x, y); float accA = x + y;
            f2unpack(aNA, x, y); accA -= (x + y);
            accA += fmaf(A, tmA, C);
            const float spA = fmaxf(accA, 0.f) + __logf(1.f + __expf(-fabsf(accA)));
            sA = vA ? spA * dtA : 0.f;
        }

        // ---- scan + weights, sub-chunk A -----------------------------------
        {
            float incl = sA;
            #pragma unroll
            for (int off = 1; off < 32; off <<= 1) {
                float v = __shfl_up_sync(0xffffffffu, incl, off);
                if (lane >= off) incl += v;
            }
            const float excl = incl - sA;
            const float w = __expf(-(carry + excl)) - __expf(-(carry + incl));
            dnum  = fmaf(w, tmA, dnum);
            carry += __shfl_sync(0xffffffffu, incl, 31);
        }
        // ---- sub-chunk B ----------------------------------------------------
        if (anyB) {
            float incl = sB;
            #pragma unroll
            for (int off = 1; off < 32; off <<= 1) {
                float v = __shfl_up_sync(0xffffffffu, incl, off);
                if (lane >= off) incl += v;
            }
            const float excl = incl - sB;
            const float w = __expf(-(carry + excl)) - __expf(-(carry + incl));
            dnum  = fmaf(w, tmB, dnum);
            carry += __shfl_sync(0xffffffffu, incl, 31);
        }
    }

    // only dnum needs a reduction; carry (total optical depth) is uniform
    #pragma unroll
    for (int off = 16; off; off >>= 1) {
        dnum += __shfl_xor_sync(0xffffffffu, dnum, off);
    }

    if (lane == 0) {
        const float opac  = -expm1f(-carry);          // telescoped Σ weights
        const float depth = dnum / fmaxf(opac, 1.17549435e-38f);
        out[2 * r    ] = opac;
        out[2 * r + 1] = depth;
    }
}

extern "C" void kernel_launch(void* const* d_in, const int* in_sizes, int n_in,
                              void* d_out, int out_size) {
    const float* rays_o      = (const float*)d_in[0];
    const float* rays_d      = (const float*)d_in[1];
    const float* W1          = (const float*)d_in[2];
    const float* b1          = (const float*)d_in[3];
    const float* W2          = (const float*)d_in[4];
    const float* b2          = (const float*)d_in[5];
    const float* t_starts    = (const float*)d_in[6];
    const float* t_ends      = (const float*)d_in[7];
    const int*   ray_indices = (const int*)d_in[8];

    const int S      = in_sizes[6];
    const int n_rays = in_sizes[0] / 3;

    float* out = (float*)d_out;

    seg_boundary_kernel<<<(S + 255) / 256, 256>>>(ray_indices, S, n_rays);

    const int warps_per_block = 8;
    const int blocks = (n_rays + warps_per_block - 1) / warps_per_block;
    render_kernel<<<blocks, warps_per_block * 32>>>(
        rays_o, rays_d, W1, b1, W2, b2, t_starts, t_ends, out, n_rays);
}

// round 10
// speedup vs baseline: 1.0580x; 1.0580x over previous
#include <cuda_runtime.h>
#include <math.h>

#define MAX_RAYS 65536
__device__ int g_seg[MAX_RAYS + 1];

typedef unsigned long long ull;

// ---- packed f32x2 helpers (Blackwell) -------------------------------------
__device__ __forceinline__ ull f2fma(ull a, ull b, ull c) {
    ull d;
    asm("fma.rn.f32x2 %0, %1, %2, %3;" : "=l"(d) : "l"(a), "l"(b), "l"(c));
    return d;
}
__device__ __forceinline__ ull f2add(ull a, ull b) {
    ull d;
    asm("add.rn.f32x2 %0, %1, %2;" : "=l"(d) : "l"(a), "l"(b));
    return d;
}
__device__ __forceinline__ ull f2pack(float lo, float hi) {
    ull d;
    asm("mov.b64 %0, {%1, %2};" : "=l"(d) : "f"(lo), "f"(hi));
    return d;
}
__device__ __forceinline__ void f2unpack(ull v, float& lo, float& hi) {
    asm("mov.b64 {%0, %1}, %2;" : "=f"(lo), "=f"(hi) : "l"(v));
}
#define ABSMASK 0x7FFFFFFF7FFFFFFFULL

// ---------------------------------------------------------------------------
// Kernel A: segment starts from sorted ray_indices (searchsorted).
// ---------------------------------------------------------------------------
__global__ void seg_boundary_kernel(const int* __restrict__ ri, int S, int n_rays) {
    const int i = blockIdx.x * blockDim.x + threadIdx.x;
    if (i >= S) return;
    const int r  = ri[i];
    const int rp = (i == 0) ? -1 : ri[i - 1];
    for (int rr = rp + 1; rr <= r; ++rr) g_seg[rr] = i;
    if (i == S - 1) {
        for (int rr = r + 1; rr <= n_rays; ++rr) g_seg[rr] = S;
    }
}

// ---------------------------------------------------------------------------
// Kernel B: one warp per ray. MLP collapsed to 1-D in t with per-ray exact
// t-bounds; constant-sign units folded into (A,C); active units compacted
// into per-warp shared pair list sQ[p] = {u2, v2} (one LDS.128 per pair).
// Main loop: 64-sample chunks; A/B scans run CONCURRENTLY (independent shfl
// chains) and B is shifted by totalA afterward -> half the scan latency.
// Opacity telescopes to 1 - exp(-total); only depth-num needs reduction.
// ---------------------------------------------------------------------------
__global__ void __launch_bounds__(128, 9) render_kernel(
    const float* __restrict__ rays_o,
    const float* __restrict__ rays_d,
    const float* __restrict__ W1,
    const float* __restrict__ b1,
    const float* __restrict__ W2,
    const float* __restrict__ b2,
    const float* __restrict__ t_starts,
    const float* __restrict__ t_ends,
    float* __restrict__ out,
    int n_rays)
{
    __shared__ ulonglong2 sQ[4][36];   // per-warp active pair list {u2, v2}

    const int wlocal  = threadIdx.x >> 5;
    const int lane    = threadIdx.x & 31;
    const int warp_id = (blockIdx.x * blockDim.x + threadIdx.x) >> 5;
    if (warp_id >= n_rays) return;
    const int r = warp_id;

    const int start = g_seg[r];
    const int end   = g_seg[r + 1];

    const float ox = __ldg(&rays_o[3 * r    ]);
    const float oy = __ldg(&rays_o[3 * r + 1]);
    const float oz = __ldg(&rays_o[3 * r + 2]);
    const float dx = __ldg(&rays_d[3 * r    ]);
    const float dy = __ldg(&rays_d[3 * r + 1]);
    const float dz = __ldg(&rays_d[3 * r + 2]);

    // ---- pre-pass: exact per-ray min/max of tm -----------------------------
    float ta = __int_as_float(0x7F800000);
    float tb = 0.f;
    for (int i0 = start; i0 < end; i0 += 32) {
        const int i = i0 + lane;
        if (i < end) {
            const float tm = 0.5f * (t_starts[i] + t_ends[i]);
            ta = fminf(ta, tm);
            tb = fmaxf(tb, tm);
        }
    }
    #pragma unroll
    for (int off = 16; off; off >>= 1) {
        ta = fminf(ta, __shfl_xor_sync(0xffffffffu, ta, off));
        tb = fmaxf(tb, __shfl_xor_sync(0xffffffffu, tb, off));
    }

    // ---- per-ray precompute (lane handles units 2*lane, 2*lane+1) ---------
    float A = 0.f, C = 0.f;
    float u0, v0, u1, v1;
    bool act0, act1, pos0, pos1;
    {
        const int j = 2 * lane;
        #pragma unroll
        for (int k = 0; k < 2; ++k) {
            const int jj = j + k;
            const float w1x = __ldg(&W1[jj]);
            const float w1y = __ldg(&W1[64 + jj]);
            const float w1z = __ldg(&W1[128 + jj]);
            const float bb  = __ldg(&b1[jj]);
            const float w2v = __ldg(&W2[jj]);
            const float hw  = 0.5f * w2v;

            const float a = fmaf(dx, w1x, fmaf(dy, w1y, dz * w1z));
            const float c = fmaf(ox, w1x, fmaf(oy, w1y, fmaf(oz, w1z, bb)));
            const float u = hw * a;
            const float v = hw * c;

            A += u;
            C += v;

            const float ya = fmaf(u, ta, v);
            const float yb = fmaf(u, tb, v);
            const bool act = (((__float_as_uint(ya) ^ __float_as_uint(yb)) >> 31) & 1u) != 0u;
            if (!act) {
                const float f = copysignf(1.f, ya + yb) * copysignf(1.f, w2v);
                A = fmaf(f, u, A);
                C = fmaf(f, v, C);
            }
            if (k == 0) { u0 = u; v0 = v; act0 = act; pos0 = (w2v >= 0.f); }
            else        { u1 = u; v1 = v; act1 = act; pos1 = (w2v >= 0.f); }
        }

        #pragma unroll
        for (int off = 16; off; off >>= 1) {
            A += __shfl_xor_sync(0xffffffffu, A, off);
            C += __shfl_xor_sync(0xffffffffu, C, off);
        }
        C += __ldg(b2);
    }

    // ---- ballot compaction into packed pair list ---------------------------
    float* qF = (float*)sQ[wlocal];

    const unsigned bp0 = __ballot_sync(0xffffffffu, act0 && pos0);
    const unsigned bn0 = __ballot_sync(0xffffffffu, act0 && !pos0);
    const unsigned bp1 = __ballot_sync(0xffffffffu, act1 && pos1);
    const unsigned bn1 = __ballot_sync(0xffffffffu, act1 && !pos1);
    const int cP0 = __popc(bp0), cN0 = __popc(bn0);
    const int cP1 = __popc(bp1), cN1 = __popc(bn1);
    const int nPos = cP0 + cP1;
    const int nNeg = cN0 + cN1;
    const int negBase = (nPos + 1) & ~1;

    const unsigned mlt = (1u << lane) - 1u;
    if (act0) {
        const int ix = pos0 ? __popc(bp0 & mlt) : (negBase + __popc(bn0 & mlt));
        qF[4 * (ix >> 1) + (ix & 1)]     = u0;
        qF[4 * (ix >> 1) + 2 + (ix & 1)] = v0;
    }
    if (act1) {
        const int ix = pos1 ? (cP0 + __popc(bp1 & mlt))
                            : (negBase + cN0 + __popc(bn1 & mlt));
        qF[4 * (ix >> 1) + (ix & 1)]     = u1;
        qF[4 * (ix >> 1) + 2 + (ix & 1)] = v1;
    }
    if (lane == 0) {
        if (nPos & 1) {
            const int ix = nPos;
            qF[4 * (ix >> 1) + (ix & 1)]     = 0.f;
            qF[4 * (ix >> 1) + 2 + (ix & 1)] = 0.f;
        }
        if (nNeg & 1) {
            const int ix = negBase + nNeg;
            qF[4 * (ix >> 1) + (ix & 1)]     = 0.f;
            qF[4 * (ix >> 1) + 2 + (ix & 1)] = 0.f;
        }
    }
    __syncwarp();

    const int pPos      = (nPos + 1) >> 1;
    const int pNegStart = negBase >> 1;
    const int pNegEnd   = pNegStart + ((nNeg + 1) >> 1);
    const ulonglong2* qq = sQ[wlocal];

    float carry = 0.f;
    float dnum  = 0.f;

    for (int i0 = start; i0 < end; i0 += 64) {
        const int  iA = i0 + lane;
        const bool vA = (iA < end);
        const int  icA = vA ? iA : (end - 1);
        const float tsA = t_starts[icA];
        const float teA = t_ends[icA];
        const float tmA = 0.5f * (tsA + teA);
        const float dtA = teA - tsA;
        const ull   t2A = f2pack(tmA, tmA);

        const bool anyB = (i0 + 32 < end);   // warp-uniform
        float sA, sB = 0.f, tmB = 0.f;

        if (anyB) {
            const int  iB = i0 + 32 + lane;
            const bool vB = (iB < end);
            const int  icB = vB ? iB : (end - 1);
            const float tsB = t_starts[icB];
            const float teB = t_ends[icB];
            tmB = 0.5f * (tsB + teB);
            const float dtB = teB - tsB;
            const ull   t2B = f2pack(tmB, tmB);

            ull aPA = 0ull, aPB = 0ull, aNA = 0ull, aNB = 0ull;
            #pragma unroll 2
            for (int p = 0; p < pPos; ++p) {
                const ulonglong2 Q = qq[p];
                const ull yA = f2fma(t2A, Q.x, Q.y);
                aPA = f2add(aPA, yA & ABSMASK);
                const ull yB = f2fma(t2B, Q.x, Q.y);
                aPB = f2add(aPB, yB & ABSMASK);
            }
            #pragma unroll 2
            for (int p = pNegStart; p < pNegEnd; ++p) {
                const ulonglong2 Q = qq[p];
                const ull yA = f2fma(t2A, Q.x, Q.y);
                aNA = f2add(aNA, yA & ABSMASK);
                const ull yB = f2fma(t2B, Q.x, Q.y);
                aNB = f2add(aNB, yB & ABSMASK);
            }
            float x, y;
            f2unpack(aPA, x, y); float accA = x + y;
            f2unpack(aNA, x, y); accA -= (x + y);
            accA += fmaf(A, tmA, C);
            f2unpack(aPB, x, y); float accB = x + y;
            f2unpack(aNB, x, y); accB -= (x + y);
            accB += fmaf(A, tmB, C);

            const float spA = fmaxf(accA, 0.f) + __logf(1.f + __expf(-fabsf(accA)));
            const float spB = fmaxf(accB, 0.f) + __logf(1.f + __expf(-fabsf(accB)));
            sA = vA ? spA * dtA : 0.f;
            sB = vB ? spB * dtB : 0.f;

            // ---- concurrent independent scans of A and B -------------------
            float inclA = sA, inclB = sB;
            #pragma unroll
            for (int off = 1; off < 32; off <<= 1) {
                const float xa = __shfl_up_sync(0xffffffffu, inclA, off);
                const float xb = __shfl_up_sync(0xffffffffu, inclB, off);
                if (lane >= off) { inclA += xa; inclB += xb; }
            }
            const float totalA = __shfl_sync(0xffffffffu, inclA, 31);
            const float totalB = __shfl_sync(0xffffffffu, inclB, 31);
            const float exclA  = inclA - sA;
            const float exclB  = inclB - sB + totalA;   // shift B by A's total
            const float inclB2 = inclB + totalA;

            // 4 independent exps -> pipelined MUFU
            const float eA0 = __expf(-(carry + exclA));
            const float eA1 = __expf(-(carry + inclA));
            const float eB0 = __expf(-(carry + exclB));
            const float eB1 = __expf(-(carry + inclB2));
            dnum = fmaf(eA0 - eA1, tmA, dnum);
            dnum = fmaf(eB0 - eB1, tmB, dnum);
            carry += totalA + totalB;
        } else {
            ull aPA = 0ull, aNA = 0ull;
            #pragma unroll 2
            for (int p = 0; p < pPos; ++p) {
                const ulonglong2 Q = qq[p];
                const ull yA = f2fma(t2A, Q.x, Q.y);
                aPA = f2add(aPA, yA & ABSMASK);
            }
            #pragma unroll 2
            for (int p = pNegStart; p < pNegEnd; ++p) {
                const ulonglong2 Q = qq[p];
                const ull yA = f2fma(t2A, Q.x, Q.y);
                aNA = f2add(aNA, yA & ABSMASK);
            }
            float x, y;
            f2unpack(aPA, x, y); float accA = x + y;
            f2unpack(aNA, x, y); accA -= (x + y);
            accA += fmaf(A, tmA, C);
            const float spA = fmaxf(accA, 0.f) + __logf(1.f + __expf(-fabsf(accA)));
            sA = vA ? spA * dtA : 0.f;

            float inclA = sA;
            #pragma unroll
            for (int off = 1; off < 32; off <<= 1) {
                const float xa = __shfl_up_sync(0xffffffffu, inclA, off);
                if (lane >= off) inclA += xa;
            }
            const float exclA = inclA - sA;
            const float eA0 = __expf(-(carry + exclA));
            const float eA1 = __expf(-(carry + inclA));
            dnum = fmaf(eA0 - eA1, tmA, dnum);
            carry += __shfl_sync(0xffffffffu, inclA, 31);
        }
    }

    // only dnum needs a reduction; carry (total optical depth) is uniform
    #pragma unroll
    for (int off = 16; off; off >>= 1) {
        dnum += __shfl_xor_sync(0xffffffffu, dnum, off);
    }

    if (lane == 0) {
        const float opac  = -expm1f(-carry);          // telescoped Σ weights
        const float depth = dnum / fmaxf(opac, 1.17549435e-38f);
        out[2 * r    ] = opac;
        out[2 * r + 1] = depth;
    }
}

extern "C" void kernel_launch(void* const* d_in, const int* in_sizes, int n_in,
                              void* d_out, int out_size) {
    const float* rays_o      = (const float*)d_in[0];
    const float* rays_d      = (const float*)d_in[1];
    const float* W1          = (const float*)d_in[2];
    const float* b1          = (const float*)d_in[3];
    const float* W2          = (const float*)d_in[4];
    const float* b2          = (const float*)d_in[5];
    const float* t_starts    = (const float*)d_in[6];
    const float* t_ends      = (const float*)d_in[7];
    const int*   ray_indices = (const int*)d_in[8];

    const int S      = in_sizes[6];
    const int n_rays = in_sizes[0] / 3;

    float* out = (float*)d_out;

    seg_boundary_kernel<<<(S + 255) / 256, 256>>>(ray_indices, S, n_rays);

    const int warps_per_block = 4;   // 128-thread blocks
    const int blocks = (n_rays + warps_per_block - 1) / warps_per_block;
    render_kernel<<<blocks, warps_per_block * 32>>>(
        rays_o, rays_d, W1, b1, W2, b2, t_starts, t_ends, out, n_rays);
}

// round 11
// speedup vs baseline: 1.1384x; 1.0760x over previous
#include <cuda_runtime.h>
#include <math.h>

#define MAX_RAYS 65536
__device__ int g_seg[MAX_RAYS + 1];

typedef unsigned long long ull;

// ---- packed f32x2 helpers (Blackwell) -------------------------------------
__device__ __forceinline__ ull f2fma(ull a, ull b, ull c) {
    ull d;
    asm("fma.rn.f32x2 %0, %1, %2, %3;" : "=l"(d) : "l"(a), "l"(b), "l"(c));
    return d;
}
__device__ __forceinline__ ull f2add(ull a, ull b) {
    ull d;
    asm("add.rn.f32x2 %0, %1, %2;" : "=l"(d) : "l"(a), "l"(b));
    return d;
}
__device__ __forceinline__ ull f2pack(float lo, float hi) {
    ull d;
    asm("mov.b64 %0, {%1, %2};" : "=l"(d) : "f"(lo), "f"(hi));
    return d;
}
__device__ __forceinline__ void f2unpack(ull v, float& lo, float& hi) {
    asm("mov.b64 {%0, %1}, %2;" : "=f"(lo), "=f"(hi) : "l"(v));
}
#define ABSMASK 0x7FFFFFFF7FFFFFFFULL

// ---------------------------------------------------------------------------
// Kernel A: segment starts from sorted ray_indices; int4-vectorized.
// ---------------------------------------------------------------------------
__global__ void seg_boundary_kernel(const int* __restrict__ ri, int S, int n_rays) {
    const int q = blockIdx.x * blockDim.x + threadIdx.x;
    const int base = q * 4;
    if (base >= S) return;

    int e0, e1, e2, e3;
    if (base + 4 <= S) {
        const int4 v = *reinterpret_cast<const int4*>(ri + base);
        e0 = v.x; e1 = v.y; e2 = v.z; e3 = v.w;
    } else {
        e0 = ri[base];
        e1 = (base + 1 < S) ? ri[base + 1] : e0;
        e2 = (base + 2 < S) ? ri[base + 2] : e1;
        e3 = (base + 3 < S) ? ri[base + 3] : e2;
    }
    const int prev = (base == 0) ? -1 : ri[base - 1];

    for (int rr = prev + 1; rr <= e0; ++rr) g_seg[rr] = base;
    if (base + 1 < S) for (int rr = e0 + 1; rr <= e1; ++rr) g_seg[rr] = base + 1;
    if (base + 2 < S) for (int rr = e1 + 1; rr <= e2; ++rr) g_seg[rr] = base + 2;
    if (base + 3 < S) for (int rr = e2 + 1; rr <= e3; ++rr) g_seg[rr] = base + 3;

    if (base + 4 >= S) {   // this quad contains the last sample
        const int lastVal = (S - 1 == base)     ? e0
                          : (S - 1 == base + 1) ? e1
                          : (S - 1 == base + 2) ? e2 : e3;
        for (int rr = lastVal + 1; rr <= n_rays; ++rr) g_seg[rr] = S;
    }
}

// ---------------------------------------------------------------------------
// Kernel B: one warp per ray. MLP collapsed to 1-D in m = ts+te (= 2*t_mid):
//   acc(m) = A m + C + Sum_j sign(w2_j)|u_j m + v_j|,
//   u = 0.25 w2 (d.W1_j)  [0.5 for half-w2, 0.5 for m=2t],
//   v = 0.5  w2 (o.W1_j + b1_j).
// Per-ray exact m-bounds from a pre-pass; constant-sign units folded into
// (A,C). Active units compacted into per-warp pair list sQ[p]={u2,v2}
// (one LDS.128/pair). 64-sample chunks; concurrent A/B scans; opacity
// telescopes; dnum accumulates w*m and is halved once at the end.
// ---------------------------------------------------------------------------
__global__ void __launch_bounds__(128, 9) render_kernel(
    const float* __restrict__ rays_o,
    const float* __restrict__ rays_d,
    const float* __restrict__ W1,
    const float* __restrict__ b1,
    const float* __restrict__ W2,
    const float* __restrict__ b2,
    const float* __restrict__ t_starts,
    const float* __restrict__ t_ends,
    float* __restrict__ out,
    int n_rays)
{
    __shared__ ulonglong2 sQ[4][36];   // per-warp active pair list {u2, v2}

    const int wlocal  = threadIdx.x >> 5;
    const int lane    = threadIdx.x & 31;
    const int warp_id = (blockIdx.x * blockDim.x + threadIdx.x) >> 5;
    if (warp_id >= n_rays) return;
    const int r = warp_id;

    const int start = g_seg[r];
    const int end   = g_seg[r + 1];

    const float ox = __ldg(&rays_o[3 * r    ]);
    const float oy = __ldg(&rays_o[3 * r + 1]);
    const float oz = __ldg(&rays_o[3 * r + 2]);
    const float dx = __ldg(&rays_d[3 * r    ]);
    const float dy = __ldg(&rays_d[3 * r + 1]);
    const float dz = __ldg(&rays_d[3 * r + 2]);

    // ---- pre-pass: exact per-ray min/max of m = ts+te ----------------------
    float ma = __int_as_float(0x7F800000);
    float mb = 0.f;
    for (int i0 = start; i0 < end; i0 += 32) {
        const int i = i0 + lane;
        if (i < end) {
            const float m = t_starts[i] + t_ends[i];
            ma = fminf(ma, m);
            mb = fmaxf(mb, m);
        }
    }
    #pragma unroll
    for (int off = 16; off; off >>= 1) {
        ma = fminf(ma, __shfl_xor_sync(0xffffffffu, ma, off));
        mb = fmaxf(mb, __shfl_xor_sync(0xffffffffu, mb, off));
    }

    // ---- per-ray precompute (lane handles units lane, lane+32) ------------
    float A, C;
    float u0, v0, u1, v1;
    bool act0, act1, pos0, pos1;
    {
        ull AC = 0ull;   // packed {A, C}
        #pragma unroll
        for (int k = 0; k < 2; ++k) {
            const int jj = lane + 32 * k;   // coalesced weight loads
            const float w1x = __ldg(&W1[jj]);
            const float w1y = __ldg(&W1[64 + jj]);
            const float w1z = __ldg(&W1[128 + jj]);
            const float bb  = __ldg(&b1[jj]);
            const float w2v = __ldg(&W2[jj]);

            const float a = fmaf(dx, w1x, fmaf(dy, w1y, dz * w1z));
            const float c = fmaf(ox, w1x, fmaf(oy, w1y, fmaf(oz, w1z, bb)));
            const float u = (0.25f * w2v) * a;   // m-space slope
            const float v = (0.5f  * w2v) * c;

            float Aadd = u, Cadd = v;

            const float ya = fmaf(u, ma, v);
            const float yb = fmaf(u, mb, v);
            const bool act = (((__float_as_uint(ya) ^ __float_as_uint(yb)) >> 31) & 1u) != 0u;
            if (!act) {
                const float f = copysignf(1.f, ya + yb) * copysignf(1.f, w2v);
                Aadd = fmaf(f, u, Aadd);
                Cadd = fmaf(f, v, Cadd);
            }
            AC = f2add(AC, f2pack(Aadd, Cadd));
            if (k == 0) { u0 = u; v0 = v; act0 = act; pos0 = (w2v >= 0.f); }
            else        { u1 = u; v1 = v; act1 = act; pos1 = (w2v >= 0.f); }
        }

        #pragma unroll
        for (int off = 16; off; off >>= 1) {
            AC = f2add(AC, __shfl_xor_sync(0xffffffffu, AC, off));
        }
        f2unpack(AC, A, C);
        C += __ldg(b2);
    }

    // ---- ballot compaction into packed pair list ---------------------------
    float* qF = (float*)sQ[wlocal];

    const unsigned bp0 = __ballot_sync(0xffffffffu, act0 && pos0);
    const unsigned bn0 = __ballot_sync(0xffffffffu, act0 && !pos0);
    const unsigned bp1 = __ballot_sync(0xffffffffu, act1 && pos1);
    const unsigned bn1 = __ballot_sync(0xffffffffu, act1 && !pos1);
    const int cP0 = __popc(bp0), cN0 = __popc(bn0);
    const int cP1 = __popc(bp1), cN1 = __popc(bn1);
    const int nPos = cP0 + cP1;
    const int nNeg = cN0 + cN1;
    const int negBase = (nPos + 1) & ~1;

    const unsigned mlt = (1u << lane) - 1u;
    if (act0) {
        const int ix = pos0 ? __popc(bp0 & mlt) : (negBase + __popc(bn0 & mlt));
        qF[4 * (ix >> 1) + (ix & 1)]     = u0;
        qF[4 * (ix >> 1) + 2 + (ix & 1)] = v0;
    }
    if (act1) {
        const int ix = pos1 ? (cP0 + __popc(bp1 & mlt))
                            : (negBase + cN0 + __popc(bn1 & mlt));
        qF[4 * (ix >> 1) + (ix & 1)]     = u1;
        qF[4 * (ix >> 1) + 2 + (ix & 1)] = v1;
    }
    if (lane == 0) {
        if (nPos & 1) {
            const int ix = nPos;
            qF[4 * (ix >> 1) + (ix & 1)]     = 0.f;
            qF[4 * (ix >> 1) + 2 + (ix & 1)] = 0.f;
        }
        if (nNeg & 1) {
            const int ix = negBase + nNeg;
            qF[4 * (ix >> 1) + (ix & 1)]     = 0.f;
            qF[4 * (ix >> 1) + 2 + (ix & 1)] = 0.f;
        }
    }
    __syncwarp();

    const int pPos      = (nPos + 1) >> 1;
    const int pNegStart = negBase >> 1;
    const int pNegEnd   = pNegStart + ((nNeg + 1) >> 1);
    const ulonglong2* qq = sQ[wlocal];

    float carry = 0.f;
    float dnum  = 0.f;    // accumulates w * m ; halved at the end

    for (int i0 = start; i0 < end; i0 += 64) {
        const int  iA = i0 + lane;
        const bool vA = (iA < end);
        const int  icA = vA ? iA : (end - 1);
        const float tsA = t_starts[icA];
        const float teA = t_ends[icA];
        const float mA  = tsA + teA;
        const float dtA = teA - tsA;
        const ull   m2A = f2pack(mA, mA);

        const bool anyB = (i0 + 32 < end);   // warp-uniform
        float sA, sB = 0.f, mB = 0.f;

        if (anyB) {
            const int  iB = i0 + 32 + lane;
            const bool vB = (iB < end);
            const int  icB = vB ? iB : (end - 1);
            const float tsB = t_starts[icB];
            const float teB = t_ends[icB];
            mB = tsB + teB;
            const float dtB = teB - tsB;
            const ull   m2B = f2pack(mB, mB);

            ull aPA = 0ull, aPB = 0ull, aNA = 0ull, aNB = 0ull;
            #pragma unroll 4
            for (int p = 0; p < pPos; ++p) {
                const ulonglong2 Q = qq[p];
                const ull yA = f2fma(m2A, Q.x, Q.y);
                aPA = f2add(aPA, yA & ABSMASK);
                const ull yB = f2fma(m2B, Q.x, Q.y);
                aPB = f2add(aPB, yB & ABSMASK);
            }
            #pragma unroll 4
            for (int p = pNegStart; p < pNegEnd; ++p) {
                const ulonglong2 Q = qq[p];
                const ull yA = f2fma(m2A, Q.x, Q.y);
                aNA = f2add(aNA, yA & ABSMASK);
                const ull yB = f2fma(m2B, Q.x, Q.y);
                aNB = f2add(aNB, yB & ABSMASK);
            }
            float x, y;
            f2unpack(aPA, x, y); float accA = x + y;
            f2unpack(aNA, x, y); accA -= (x + y);
            accA += fmaf(A, mA, C);
            f2unpack(aPB, x, y); float accB = x + y;
            f2unpack(aNB, x, y); accB -= (x + y);
            accB += fmaf(A, mB, C);

            const float spA = fmaxf(accA, 0.f) + __logf(1.f + __expf(-fabsf(accA)));
            const float spB = fmaxf(accB, 0.f) + __logf(1.f + __expf(-fabsf(accB)));
            sA = vA ? spA * dtA : 0.f;
            sB = vB ? spB * dtB : 0.f;

            // concurrent independent scans of A and B
            float inclA = sA, inclB = sB;
            #pragma unroll
            for (int off = 1; off < 32; off <<= 1) {
                const float xa = __shfl_up_sync(0xffffffffu, inclA, off);
                const float xb = __shfl_up_sync(0xffffffffu, inclB, off);
                if (lane >= off) { inclA += xa; inclB += xb; }
            }
            const float totalA = __shfl_sync(0xffffffffu, inclA, 31);
            const float totalB = __shfl_sync(0xffffffffu, inclB, 31);
            const float exclA  = inclA - sA;
            const float exclB  = inclB - sB + totalA;
            const float inclB2 = inclB + totalA;

            const float eA0 = __expf(-(carry + exclA));
            const float eA1 = __expf(-(carry + inclA));
            const float eB0 = __expf(-(carry + exclB));
            const float eB1 = __expf(-(carry + inclB2));
            dnum = fmaf(eA0 - eA1, mA, dnum);
            dnum = fmaf(eB0 - eB1, mB, dnum);
            carry += totalA + totalB;
        } else {
            ull aPA = 0ull, aNA = 0ull;
            #pragma unroll 4
            for (int p = 0; p < pPos; ++p) {
                const ulonglong2 Q = qq[p];
                const ull yA = f2fma(m2A, Q.x, Q.y);
                aPA = f2add(aPA, yA & ABSMASK);
            }
            #pragma unroll 4
            for (int p = pNegStart; p < pNegEnd; ++p) {
                const ulonglong2 Q = qq[p];
                const ull yA = f2fma(m2A, Q.x, Q.y);
                aNA = f2add(aNA, yA & ABSMASK);
            }
            float x, y;
            f2unpack(aPA, x, y); float accA = x + y;
            f2unpack(aNA, x, y); accA -= (x + y);
            accA += fmaf(A, mA, C);
            const float spA = fmaxf(accA, 0.f) + __logf(1.f + __expf(-fabsf(accA)));
            sA = vA ? spA * dtA : 0.f;

            float inclA = sA;
            #pragma unroll
            for (int off = 1; off < 32; off <<= 1) {
                const float xa = __shfl_up_sync(0xffffffffu, inclA, off);
                if (lane >= off) inclA += xa;
            }
            const float exclA = inclA - sA;
            const float eA0 = __expf(-(carry + exclA));
            const float eA1 = __expf(-(carry + inclA));
            dnum = fmaf(eA0 - eA1, mA, dnum);
            carry += __shfl_sync(0xffffffffu, inclA, 31);
        }
    }

    // only dnum needs a reduction; carry (total optical depth) is uniform
    #pragma unroll
    for (int off = 16; off; off >>= 1) {
        dnum += __shfl_xor_sync(0xffffffffu, dnum, off);
    }

    if (lane == 0) {
        const float opac  = -expm1f(-carry);
        const float depth = (0.5f * dnum) / fmaxf(opac, 1.17549435e-38f);
        out[2 * r    ] = opac;
        out[2 * r + 1] = depth;
    }
}

extern "C" void kernel_launch(void* const* d_in, const int* in_sizes, int n_in,
                              void* d_out, int out_size) {
    const float* rays_o      = (const float*)d_in[0];
    const float* rays_d      = (const float*)d_in[1];
    const float* W1          = (const float*)d_in[2];
    const float* b1          = (const float*)d_in[3];
    const float* W2          = (const float*)d_in[4];
    const float* b2          = (const float*)d_in[5];
    const float* t_starts    = (const float*)d_in[6];
    const float* t_ends      = (const float*)d_in[7];
    const int*   ray_indices = (const int*)d_in[8];

    const int S      = in_sizes[6];
    const int n_rays = in_sizes[0] / 3;

    float* out = (float*)d_out;

    const int quads = (S + 3) / 4;
    seg_boundary_kernel<<<(quads + 255) / 256, 256>>>(ray_indices, S, n_rays);

    const int warps_per_block = 4;   // 128-thread blocks
    const int blocks = (n_rays + warps_per_block - 1) / warps_per_block;
    render_kernel<<<blocks, warps_per_block * 32>>>(
        rays_o, rays_d, W1, b1, W2, b2, t_starts, t_ends, out, n_rays);
}